// round 5
// baseline (speedup 1.0000x reference)
#include <cuda_runtime.h>
#include <cstdint>

#define BH_N    128
#define M_TOTAL 512
#define L_SPAN  2048
#define HD      128
#define KV_LEN  (M_TOTAL + L_SPAN)   // 2560
#define BM      64
#define BN      64
#define NKT     33
#define THREADS 512                   // 16 warps: 4 row-groups x 4 column-quarters

// SMEM strides (floats) chosen for conflict-free mma fragment loads
#define QS_STRIDE 132   // %32==4 -> A-frag bank = 4g+tg (distinct)
#define KS_STRIDE 132
#define VS_STRIDE 136   // %32==8 -> B-frag bank = 8tg+g (distinct)
#define PT_STRIDE 72    // %32==8
#define RG_STRIDE 132

#define QS_OFF 0
#define KS_OFF (QS_OFF + BM * QS_STRIDE)
#define VS_OFF (KS_OFF + BN * KS_STRIDE)
#define PT_OFF (VS_OFF + BN * VS_STRIDE)
#define RG_OFF (PT_OFF + HD * PT_STRIDE)
#define EX_OFF (RG_OFF + BM * RG_STRIDE)   // 4 x 64 exchange (max / sum)
#define SMEM_FLOATS (EX_OFF + 4 * BM)
#define SMEM_BYTES  (SMEM_FLOATS * 4)

__device__ __forceinline__ uint32_t f2tf(float x) {
    uint32_t r;
    asm("cvt.rna.tf32.f32 %0, %1;" : "=r"(r) : "f"(x));
    return r;
}

__device__ __forceinline__ void mma_tf32(float* d, const uint32_t* a, const uint32_t* b) {
    asm volatile(
        "mma.sync.aligned.m16n8k8.row.col.f32.tf32.tf32.f32 "
        "{%0,%1,%2,%3}, {%4,%5,%6,%7}, {%8,%9}, {%0,%1,%2,%3};\n"
        : "+f"(d[0]), "+f"(d[1]), "+f"(d[2]), "+f"(d[3])
        : "r"(a[0]), "r"(a[1]), "r"(a[2]), "r"(a[3]), "r"(b[0]), "r"(b[1]));
}

extern "C" __global__ void __launch_bounds__(THREADS, 1)
seq_attn_kernel(const float* __restrict__ Q, const float* __restrict__ K,
                const float* __restrict__ V, const float* __restrict__ PE,
                float* __restrict__ OUT)
{
    extern __shared__ float sm[];
    uint32_t* smu = reinterpret_cast<uint32_t*>(sm);

    const int tid  = threadIdx.x;
    const int warp = tid >> 5;
    const int lane = tid & 31;
    const int g    = lane >> 2;
    const int tg   = lane & 3;
    const int wg   = warp & 3;        // row group 0..3
    const int qtr  = warp >> 2;       // column quarter 0..3
    const int wrow = wg * 16;
    const int ntb  = qtr * 2;         // QK/pos: this quarter's 2 n8-tiles (16 key cols)
    const int colb = qtr * 4;         // PV:     this quarter's 4 n8-tiles (32 out cols)
    const int m0   = blockIdx.x * BM;
    const int b    = blockIdx.y;

    const float qscale = 0.08838834764831845f;  // 1/sqrt(128) folded into Q

    // ---- load Q tile (scaled, tf32) ----
    {
        const float* gq = Q + ((size_t)b * M_TOTAL + m0) * HD;
        for (int r = warp; r < BM; r += 16) {
            float4 x = *reinterpret_cast<const float4*>(gq + r * HD + lane * 4);
            uint32_t* dst = smu + QS_OFF + r * QS_STRIDE + lane * 4;
            dst[0] = f2tf(x.x * qscale); dst[1] = f2tf(x.y * qscale);
            dst[2] = f2tf(x.z * qscale); dst[3] = f2tf(x.w * qscale);
        }
    }

    float O[4][4];                    // 4 n8-tiles over this quarter's 32 out cols
#pragma unroll
    for (int n = 0; n < 4; ++n)
#pragma unroll
        for (int e = 0; e < 4; ++e) O[n][e] = 0.f;

    float m0r = -1e30f, m1r = -1e30f;  // running row max (rows r0, r1) — same in all quarters
    float l0r = 0.f,    l1r = 0.f;     // running sumexp, THIS quarter's columns (lane-partial)

    const int r0 = wrow + g, r1 = wrow + g + 8;

    for (int t = 0; t < NKT; ++t) {
        __syncthreads();  // prev-iter consumers of Ks/Vs/Pt done

        const int k0 = m0 + t * BN;
        // ---- load K/V tiles (always in-bounds) ----
        {
            const float* gk = K + ((size_t)b * KV_LEN + k0) * HD;
            const float* gv = V + ((size_t)b * KV_LEN + k0) * HD;
            for (int r = warp; r < BN; r += 16) {
                float4 xk = *reinterpret_cast<const float4*>(gk + r * HD + lane * 4);
                uint32_t* dk = smu + KS_OFF + r * KS_STRIDE + lane * 4;
                dk[0] = f2tf(xk.x); dk[1] = f2tf(xk.y);
                dk[2] = f2tf(xk.z); dk[3] = f2tf(xk.w);
                float4 xv = *reinterpret_cast<const float4*>(gv + r * HD + lane * 4);
                uint32_t* dv = smu + VS_OFF + r * VS_STRIDE + lane * 4;
                dv[0] = f2tf(xv.x); dv[1] = f2tf(xv.y);
                dv[2] = f2tf(xv.z); dv[3] = f2tf(xv.w);
            }
        }
        const bool do_pos = (t < (L_SPAN / BN));
        if (do_pos) {
            const float* gp = PE + t * BN;
            const int pc = tid & 15, pr = tid >> 4;
            for (int d = pr; d < HD; d += 32) {
                float4 x = *reinterpret_cast<const float4*>(gp + (size_t)d * L_SPAN + pc * 4);
                uint32_t* dp = smu + PT_OFF + d * PT_STRIDE + pc * 4;
                dp[0] = f2tf(x.x); dp[1] = f2tf(x.y);
                dp[2] = f2tf(x.z); dp[3] = f2tf(x.w);
            }
        }
        __syncthreads();

        // ---- S = Q @ K^T and Spos = Q @ Pblk (this quarter's 2 n-tiles) ----
        float s[2][4], sp[2][4];
#pragma unroll
        for (int n = 0; n < 2; ++n)
#pragma unroll
            for (int e = 0; e < 4; ++e) { s[n][e] = 0.f; sp[n][e] = 0.f; }

#pragma unroll 1
        for (int ks = 0; ks < 16; ++ks) {
            uint32_t a[4];
            const uint32_t* qb = smu + QS_OFF + r0 * QS_STRIDE + ks * 8 + tg;
            a[0] = qb[0];
            a[1] = qb[8 * QS_STRIDE];
            a[2] = qb[4];
            a[3] = qb[8 * QS_STRIDE + 4];
#pragma unroll
            for (int nt = 0; nt < 2; ++nt) {
                uint32_t bk[2];
                const uint32_t* kb = smu + KS_OFF + ((ntb + nt) * 8 + g) * KS_STRIDE + ks * 8 + tg;
                bk[0] = kb[0]; bk[1] = kb[4];
                mma_tf32(s[nt], a, bk);
            }
            if (do_pos) {
#pragma unroll
                for (int nt = 0; nt < 2; ++nt) {
                    uint32_t bp[2];
                    const uint32_t* pb = smu + PT_OFF + (ks * 8 + tg) * PT_STRIDE + (ntb + nt) * 8 + g;
                    bp[0] = pb[0]; bp[1] = pb[4 * PT_STRIDE];
                    mma_tf32(sp[nt], a, bp);
                }
            }
        }

        // ---- Spos -> ring buffer (quarters write disjoint columns) ----
        if (do_pos) {
            const int base = (t & 1) * BN;
            float* rg = sm + RG_OFF;
#pragma unroll
            for (int nt = 0; nt < 2; ++nt) {
                const int c = (ntb + nt) * 8 + tg * 2;
                rg[r0 * RG_STRIDE + base + c]     = sp[nt][0];
                rg[r0 * RG_STRIDE + base + c + 1] = sp[nt][1];
                rg[r1 * RG_STRIDE + base + c]     = sp[nt][2];
                rg[r1 * RG_STRIDE + base + c + 1] = sp[nt][3];
            }
        }
        __syncthreads();  // ring reads cross column-quarters

        // ---- add positional logit (l = 64t + j - i), mask window ----
        {
            const float* rg = sm + RG_OFF;
#pragma unroll
            for (int nt = 0; nt < 2; ++nt) {
#pragma unroll
                for (int e = 0; e < 4; ++e) {
                    const int j = (ntb + nt) * 8 + tg * 2 + (e & 1);
                    const int r = (e < 2) ? r0 : r1;
                    const int l = t * BN + j - r;
                    if (l >= 0 && l < L_SPAN)
                        s[nt][e] += rg[r * RG_STRIDE + (l & 127)];
                    else
                        s[nt][e] = -1e30f;
                }
            }
        }

        // ---- online softmax: local max, then cross-quarter exchange ----
        float ml0 = -1e30f, ml1 = -1e30f;
#pragma unroll
        for (int nt = 0; nt < 2; ++nt) {
            ml0 = fmaxf(ml0, fmaxf(s[nt][0], s[nt][1]));
            ml1 = fmaxf(ml1, fmaxf(s[nt][2], s[nt][3]));
        }
        ml0 = fmaxf(ml0, __shfl_xor_sync(0xffffffffu, ml0, 1));
        ml0 = fmaxf(ml0, __shfl_xor_sync(0xffffffffu, ml0, 2));
        ml1 = fmaxf(ml1, __shfl_xor_sync(0xffffffffu, ml1, 1));
        ml1 = fmaxf(ml1, __shfl_xor_sync(0xffffffffu, ml1, 2));

        float* ex = sm + EX_OFF;
        if (tg == 0) {
            ex[qtr * BM + r0] = ml0;
            ex[qtr * BM + r1] = ml1;
        }
        __syncthreads();
#pragma unroll
        for (int qq = 0; qq < 4; ++qq) {
            ml0 = fmaxf(ml0, ex[qq * BM + r0]);
            ml1 = fmaxf(ml1, ex[qq * BM + r1]);
        }

        const float mn0 = fmaxf(m0r, ml0);
        const float mn1 = fmaxf(m1r, ml1);
        const float al0 = __expf(m0r - mn0);
        const float al1 = __expf(m1r - mn1);
        m0r = mn0; m1r = mn1;

        float ps0 = 0.f, ps1 = 0.f;
#pragma unroll
        for (int nt = 0; nt < 2; ++nt) {
            s[nt][0] = __expf(s[nt][0] - mn0);
            s[nt][1] = __expf(s[nt][1] - mn0);
            s[nt][2] = __expf(s[nt][2] - mn1);
            s[nt][3] = __expf(s[nt][3] - mn1);
            ps0 += s[nt][0] + s[nt][1];
            ps1 += s[nt][2] + s[nt][3];
        }
        l0r = l0r * al0 + ps0;
        l1r = l1r * al1 + ps1;

#pragma unroll
        for (int n = 0; n < 4; ++n) {
            O[n][0] *= al0; O[n][1] *= al0;
            O[n][2] *= al1; O[n][3] *= al1;
        }

        // ---- probs -> PT buffer (reuse; pos-B reads completed before syncs above) ----
        {
            uint32_t* pu = smu + PT_OFF;
#pragma unroll
            for (int nt = 0; nt < 2; ++nt) {
                const int c = (ntb + nt) * 8 + tg * 2;
                pu[r0 * PT_STRIDE + c]     = f2tf(s[nt][0]);
                pu[r0 * PT_STRIDE + c + 1] = f2tf(s[nt][1]);
                pu[r1 * PT_STRIDE + c]     = f2tf(s[nt][2]);
                pu[r1 * PT_STRIDE + c + 1] = f2tf(s[nt][3]);
            }
        }
        __syncthreads();  // PV reads probs across all quarters

        // ---- O += P @ V (this quarter's 32 output columns) ----
#pragma unroll 1
        for (int ks = 0; ks < 8; ++ks) {
            uint32_t a[4];
            const uint32_t* pb = smu + PT_OFF + r0 * PT_STRIDE + ks * 8 + tg;
            a[0] = pb[0];
            a[1] = pb[8 * PT_STRIDE];
            a[2] = pb[4];
            a[3] = pb[8 * PT_STRIDE + 4];
#pragma unroll
            for (int nt = 0; nt < 4; ++nt) {
                uint32_t bv[2];
                const uint32_t* vb = smu + VS_OFF + (ks * 8 + tg) * VS_STRIDE + (colb + nt) * 8 + g;
                bv[0] = vb[0]; bv[1] = vb[4 * VS_STRIDE];
                mma_tf32(O[nt], a, bv);
            }
        }
    }

    // ---- epilogue: cross-quarter sumexp reduction, normalize, store ----
    l0r += __shfl_xor_sync(0xffffffffu, l0r, 1);
    l0r += __shfl_xor_sync(0xffffffffu, l0r, 2);
    l1r += __shfl_xor_sync(0xffffffffu, l1r, 1);
    l1r += __shfl_xor_sync(0xffffffffu, l1r, 2);

    float* ex = sm + EX_OFF;
    __syncthreads();             // last tile's exchange reads done before overwrite
    if (tg == 0) {
        ex[qtr * BM + r0] = l0r;
        ex[qtr * BM + r1] = l1r;
    }
    __syncthreads();
    float t0 = 0.f, t1 = 0.f;
#pragma unroll
    for (int qq = 0; qq < 4; ++qq) {
        t0 += ex[qq * BM + r0];
        t1 += ex[qq * BM + r1];
    }
    const float i0 = 1.f / t0;
    const float i1 = 1.f / t1;

    float* go = OUT + ((size_t)b * M_TOTAL + m0) * HD;
#pragma unroll
    for (int nt = 0; nt < 4; ++nt) {
        const int c = (colb + nt) * 8 + tg * 2;
        float2 o0 = make_float2(O[nt][0] * i0, O[nt][1] * i0);
        *reinterpret_cast<float2*>(go + r0 * HD + c) = o0;
        float2 o1 = make_float2(O[nt][2] * i1, O[nt][3] * i1);
        *reinterpret_cast<float2*>(go + r1 * HD + c) = o1;
    }
}

extern "C" void kernel_launch(void* const* d_in, const int* in_sizes, int n_in,
                              void* d_out, int out_size) {
    const float* q  = (const float*)d_in[0];
    const float* k  = (const float*)d_in[1];
    const float* v  = (const float*)d_in[2];
    const float* pe = (const float*)d_in[3];
    float* out = (float*)d_out;

    cudaFuncSetAttribute(seq_attn_kernel,
                         cudaFuncAttributeMaxDynamicSharedMemorySize, SMEM_BYTES);

    dim3 grid(M_TOTAL / BM, BH_N);
    seq_attn_kernel<<<grid, THREADS, SMEM_BYTES>>>(q, k, v, pe, out);
}

// round 6
// speedup vs baseline: 1.3359x; 1.3359x over previous
#include <cuda_runtime.h>
#include <cstdint>

#define BH_N    128
#define M_TOTAL 512
#define L_SPAN  2048
#define HD      128
#define KV_LEN  (M_TOTAL + L_SPAN)   // 2560
#define BM      64
#define BN      64
#define NKT     33
#define NPOS    32                    // pos blocks: t < 32
#define THREADS 256                   // 8 warps: 4 row-groups x 2 column-halves

// SMEM strides (floats) chosen for conflict-free mma fragment loads
#define QS_STRIDE 132   // %32==4 -> A-frag bank = 4g+tg (distinct)
#define KS_STRIDE 132
#define VS_STRIDE 136   // %32==8 -> B-frag bank = 8tg+g (distinct)
#define PT_STRIDE 72    // %32==8
#define PB_STRIDE 72
#define RG_STRIDE 132

#define QS_OFF 0
#define KS_OFF (QS_OFF + BM * QS_STRIDE)
#define VS_OFF (KS_OFF + BN * KS_STRIDE)
#define PT_OFF (VS_OFF + BN * VS_STRIDE)
#define RG_OFF (PT_OFF + HD * PT_STRIDE)
#define PB_OFF (RG_OFF + BM * RG_STRIDE)
#define EX_OFF (PB_OFF + BM * PB_STRIDE)   // 2 x 64 exchange (max / sum)
#define SMEM_FLOATS (EX_OFF + 2 * BM)
#define SMEM_BYTES  (SMEM_FLOATS * 4)

__device__ __forceinline__ uint32_t f2tf(float x) {
    uint32_t r;
    asm("cvt.rna.tf32.f32 %0, %1;" : "=r"(r) : "f"(x));
    return r;
}

__device__ __forceinline__ void mma_tf32(float* d, const uint32_t* a, const uint32_t* b) {
    asm volatile(
        "mma.sync.aligned.m16n8k8.row.col.f32.tf32.tf32.f32 "
        "{%0,%1,%2,%3}, {%4,%5,%6,%7}, {%8,%9}, {%0,%1,%2,%3};\n"
        : "+f"(d[0]), "+f"(d[1]), "+f"(d[2]), "+f"(d[3])
        : "r"(a[0]), "r"(a[1]), "r"(a[2]), "r"(a[3]), "r"(b[0]), "r"(b[1]));
}

extern "C" __global__ void __launch_bounds__(THREADS, 1)
seq_attn_kernel(const float* __restrict__ Q, const float* __restrict__ K,
                const float* __restrict__ V, const float* __restrict__ PE,
                float* __restrict__ OUT)
{
    extern __shared__ float sm[];
    uint32_t* smu = reinterpret_cast<uint32_t*>(sm);

    const int tid  = threadIdx.x;
    const int warp = tid >> 5;
    const int lane = tid & 31;
    const int g    = lane >> 2;
    const int tg   = lane & 3;
    const int wg   = warp & 3;        // row group 0..3
    const int half = warp >> 2;       // column half 0..1
    const int wrow = wg * 16;
    const int ntb  = half * 4;        // QK/pos: this half's 4 n8-tiles (32 key cols)
    const int colb = half * 8;        // PV:     this half's 8 n8-tiles (64 out cols)
    const int m0   = blockIdx.x * BM;
    const int b    = blockIdx.y;

    const float qscale = 0.08838834764831845f;  // 1/sqrt(128) folded into Q

    // base pointers for staged loads
    const float* gkb = K + (size_t)b * KV_LEN * HD + (size_t)m0 * HD;
    const float* gvb = V + (size_t)b * KV_LEN * HD + (size_t)m0 * HD;
    const int pc = tid & 15, pr = tid >> 4;   // P-load mapping: 16 lanes x 16 rows

    // ---- load Q tile (scaled, tf32) ----
    {
        const float* gq = Q + ((size_t)b * M_TOTAL + m0) * HD;
        for (int r = warp; r < BM; r += 8) {
            float4 x = *reinterpret_cast<const float4*>(gq + r * HD + lane * 4);
            uint32_t* dst = smu + QS_OFF + r * QS_STRIDE + lane * 4;
            dst[0] = f2tf(x.x * qscale); dst[1] = f2tf(x.y * qscale);
            dst[2] = f2tf(x.z * qscale); dst[3] = f2tf(x.w * qscale);
        }
    }

    // ---- register staging for tile 0 ----
    float4 stK[8], stV[8], stP[8];
    {
#pragma unroll
        for (int i = 0; i < 8; ++i) {
            const int r = warp + 8 * i;
            stK[i] = *reinterpret_cast<const float4*>(gkb + r * HD + lane * 4);
            stV[i] = *reinterpret_cast<const float4*>(gvb + r * HD + lane * 4);
        }
#pragma unroll
        for (int i = 0; i < 8; ++i) {
            const int d = pr + 16 * i;
            stP[i] = *reinterpret_cast<const float4*>(PE + (size_t)d * L_SPAN + pc * 4);
        }
    }

    float O[8][4];
#pragma unroll
    for (int n = 0; n < 8; ++n)
#pragma unroll
        for (int e = 0; e < 4; ++e) O[n][e] = 0.f;

    float m0r = -1e30f, m1r = -1e30f;
    float l0r = 0.f,    l1r = 0.f;

    const int r0 = wrow + g, r1 = wrow + g + 8;

    for (int t = 0; t < NKT; ++t) {
        const bool do_pos = (t < NPOS);

        // ---- publish staged tile t to SMEM (buffers free from t-1) ----
#pragma unroll
        for (int i = 0; i < 8; ++i) {
            const int r = warp + 8 * i;
            uint32_t* dk = smu + KS_OFF + r * KS_STRIDE + lane * 4;
            dk[0] = f2tf(stK[i].x); dk[1] = f2tf(stK[i].y);
            dk[2] = f2tf(stK[i].z); dk[3] = f2tf(stK[i].w);
            uint32_t* dv = smu + VS_OFF + r * VS_STRIDE + lane * 4;
            dv[0] = f2tf(stV[i].x); dv[1] = f2tf(stV[i].y);
            dv[2] = f2tf(stV[i].z); dv[3] = f2tf(stV[i].w);
        }
        if (do_pos) {
#pragma unroll
            for (int i = 0; i < 8; ++i) {
                const int d = pr + 16 * i;
                uint32_t* dp = smu + PT_OFF + d * PT_STRIDE + pc * 4;
                dp[0] = f2tf(stP[i].x); dp[1] = f2tf(stP[i].y);
                dp[2] = f2tf(stP[i].z); dp[3] = f2tf(stP[i].w);
            }
        }
        __syncthreads();   // S1: tile t visible everywhere

        // ---- issue LDGs for tile t+1 into registers (hidden under QK) ----
        if (t + 1 < NKT) {
            const float* gk = gkb + (size_t)(t + 1) * BN * HD;
            const float* gv = gvb + (size_t)(t + 1) * BN * HD;
#pragma unroll
            for (int i = 0; i < 8; ++i) {
                const int r = warp + 8 * i;
                stK[i] = *reinterpret_cast<const float4*>(gk + r * HD + lane * 4);
                stV[i] = *reinterpret_cast<const float4*>(gv + r * HD + lane * 4);
            }
            if (t + 1 < NPOS) {
                const float* gp = PE + (t + 1) * BN;
#pragma unroll
                for (int i = 0; i < 8; ++i) {
                    const int d = pr + 16 * i;
                    stP[i] = *reinterpret_cast<const float4*>(gp + (size_t)d * L_SPAN + pc * 4);
                }
            }
        }

        // ---- S = Q @ K^T and Spos = Q @ Pblk (this half's 4 n-tiles) ----
        float s[4][4], sp[4][4];
#pragma unroll
        for (int n = 0; n < 4; ++n)
#pragma unroll
            for (int e = 0; e < 4; ++e) { s[n][e] = 0.f; sp[n][e] = 0.f; }

#pragma unroll 2
        for (int ks = 0; ks < 16; ++ks) {
            uint32_t a[4];
            const uint32_t* qb = smu + QS_OFF + r0 * QS_STRIDE + ks * 8 + tg;
            a[0] = qb[0];
            a[1] = qb[8 * QS_STRIDE];
            a[2] = qb[4];
            a[3] = qb[8 * QS_STRIDE + 4];
#pragma unroll
            for (int nt = 0; nt < 4; ++nt) {
                uint32_t bk[2];
                const uint32_t* kb = smu + KS_OFF + ((ntb + nt) * 8 + g) * KS_STRIDE + ks * 8 + tg;
                bk[0] = kb[0]; bk[1] = kb[4];
                mma_tf32(s[nt], a, bk);
            }
            if (do_pos) {
#pragma unroll
                for (int nt = 0; nt < 4; ++nt) {
                    uint32_t bp[2];
                    const uint32_t* pb = smu + PT_OFF + (ks * 8 + tg) * PT_STRIDE + (ntb + nt) * 8 + g;
                    bp[0] = pb[0]; bp[1] = pb[4 * PT_STRIDE];
                    mma_tf32(sp[nt], a, bp);
                }
            }
        }

        // ---- Spos -> ring buffer (halves write disjoint columns) ----
        if (do_pos) {
            const int base = (t & 1) * BN;
            float* rg = sm + RG_OFF;
#pragma unroll
            for (int nt = 0; nt < 4; ++nt) {
                const int c = (ntb + nt) * 8 + tg * 2;
                rg[r0 * RG_STRIDE + base + c]     = sp[nt][0];
                rg[r0 * RG_STRIDE + base + c + 1] = sp[nt][1];
                rg[r1 * RG_STRIDE + base + c]     = sp[nt][2];
                rg[r1 * RG_STRIDE + base + c + 1] = sp[nt][3];
            }
        }
        __syncthreads();   // S2: ring visible (cross-half reads)

        // ---- add positional logit (l = 64t + j - i), mask window ----
        {
            const float* rg = sm + RG_OFF;
#pragma unroll
            for (int nt = 0; nt < 4; ++nt) {
#pragma unroll
                for (int e = 0; e < 4; ++e) {
                    const int j = (ntb + nt) * 8 + tg * 2 + (e & 1);
                    const int r = (e < 2) ? r0 : r1;
                    const int l = t * BN + j - r;
                    if (l >= 0 && l < L_SPAN)
                        s[nt][e] += rg[r * RG_STRIDE + (l & 127)];
                    else
                        s[nt][e] = -1e30f;
                }
            }
        }

        // ---- online softmax: local max, then cross-half exchange ----
        float ml0 = -1e30f, ml1 = -1e30f;
#pragma unroll
        for (int nt = 0; nt < 4; ++nt) {
            ml0 = fmaxf(ml0, fmaxf(s[nt][0], s[nt][1]));
            ml1 = fmaxf(ml1, fmaxf(s[nt][2], s[nt][3]));
        }
        ml0 = fmaxf(ml0, __shfl_xor_sync(0xffffffffu, ml0, 1));
        ml0 = fmaxf(ml0, __shfl_xor_sync(0xffffffffu, ml0, 2));
        ml1 = fmaxf(ml1, __shfl_xor_sync(0xffffffffu, ml1, 1));
        ml1 = fmaxf(ml1, __shfl_xor_sync(0xffffffffu, ml1, 2));

        float* ex = sm + EX_OFF;
        if (tg == 0) {
            ex[half * BM + r0] = ml0;
            ex[half * BM + r1] = ml1;
        }
        __syncthreads();   // S3: exchange visible
        ml0 = fmaxf(ml0, ex[(1 - half) * BM + r0]);
        ml1 = fmaxf(ml1, ex[(1 - half) * BM + r1]);

        const float mn0 = fmaxf(m0r, ml0);
        const float mn1 = fmaxf(m1r, ml1);
        const float al0 = __expf(m0r - mn0);
        const float al1 = __expf(m1r - mn1);
        m0r = mn0; m1r = mn1;

        float ps0 = 0.f, ps1 = 0.f;
#pragma unroll
        for (int nt = 0; nt < 4; ++nt) {
            s[nt][0] = __expf(s[nt][0] - mn0);
            s[nt][1] = __expf(s[nt][1] - mn0);
            s[nt][2] = __expf(s[nt][2] - mn1);
            s[nt][3] = __expf(s[nt][3] - mn1);
            ps0 += s[nt][0] + s[nt][1];
            ps1 += s[nt][2] + s[nt][3];
        }
        l0r = l0r * al0 + ps0;
        l1r = l1r * al1 + ps1;

#pragma unroll
        for (int n = 0; n < 8; ++n) {
            O[n][0] *= al0; O[n][1] *= al0;
            O[n][2] *= al1; O[n][3] *= al1;
        }

        // ---- probs -> dedicated PB buffer ----
        {
            uint32_t* pu = smu + PB_OFF;
#pragma unroll
            for (int nt = 0; nt < 4; ++nt) {
                const int c = (ntb + nt) * 8 + tg * 2;
                pu[r0 * PB_STRIDE + c]     = f2tf(s[nt][0]);
                pu[r0 * PB_STRIDE + c + 1] = f2tf(s[nt][1]);
                pu[r1 * PB_STRIDE + c]     = f2tf(s[nt][2]);
                pu[r1 * PB_STRIDE + c + 1] = f2tf(s[nt][3]);
            }
        }
        __syncthreads();   // S4: probs visible

        // ---- O += P @ V (this half's 64 output columns) ----
#pragma unroll 2
        for (int ks = 0; ks < 8; ++ks) {
            uint32_t a[4];
            const uint32_t* pb = smu + PB_OFF + r0 * PB_STRIDE + ks * 8 + tg;
            a[0] = pb[0];
            a[1] = pb[8 * PB_STRIDE];
            a[2] = pb[4];
            a[3] = pb[8 * PB_STRIDE + 4];
#pragma unroll
            for (int nt = 0; nt < 8; ++nt) {
                uint32_t bv[2];
                const uint32_t* vb = smu + VS_OFF + (ks * 8 + tg) * VS_STRIDE + (colb + nt) * 8 + g;
                bv[0] = vb[0]; bv[1] = vb[4 * VS_STRIDE];
                mma_tf32(O[nt], a, bv);
            }
        }
        __syncthreads();   // S5: PV done -> K/V/P buffers free for next publish
    }

    // ---- epilogue: cross-half sumexp reduction, normalize, store ----
    l0r += __shfl_xor_sync(0xffffffffu, l0r, 1);
    l0r += __shfl_xor_sync(0xffffffffu, l0r, 2);
    l1r += __shfl_xor_sync(0xffffffffu, l1r, 1);
    l1r += __shfl_xor_sync(0xffffffffu, l1r, 2);

    float* ex = sm + EX_OFF;
    if (tg == 0) {
        ex[half * BM + r0] = l0r;
        ex[half * BM + r1] = l1r;
    }
    __syncthreads();
    const float i0 = 1.f / (l0r + ex[(1 - half) * BM + r0]);
    const float i1 = 1.f / (l1r + ex[(1 - half) * BM + r1]);

    float* go = OUT + ((size_t)b * M_TOTAL + m0) * HD;
#pragma unroll
    for (int nt = 0; nt < 8; ++nt) {
        const int c = (colb + nt) * 8 + tg * 2;
        float2 o0 = make_float2(O[nt][0] * i0, O[nt][1] * i0);
        *reinterpret_cast<float2*>(go + r0 * HD + c) = o0;
        float2 o1 = make_float2(O[nt][2] * i1, O[nt][3] * i1);
        *reinterpret_cast<float2*>(go + r1 * HD + c) = o1;
    }
}

extern "C" void kernel_launch(void* const* d_in, const int* in_sizes, int n_in,
                              void* d_out, int out_size) {
    const float* q  = (const float*)d_in[0];
    const float* k  = (const float*)d_in[1];
    const float* v  = (const float*)d_in[2];
    const float* pe = (const float*)d_in[3];
    float* out = (float*)d_out;

    cudaFuncSetAttribute(seq_attn_kernel,
                         cudaFuncAttributeMaxDynamicSharedMemorySize, SMEM_BYTES);

    dim3 grid(M_TOTAL / BM, BH_N);
    seq_attn_kernel<<<grid, THREADS, SMEM_BYTES>>>(q, k, v, pe, out);
}